// round 16
// baseline (speedup 1.0000x reference)
#include <cuda_runtime.h>
#include <cstdint>

#define SEQ     256
#define BATCH   512
#define IN_DIM  256
#define HDIM    8
#define DIN     264          // IN_DIM + HDIM
#define NROWS   (SEQ * BATCH)

// Scratch: pre-activations, bias folded in.
// Layout: zx[(t*BATCH + b)*32 + (g*8 + q)]  (column = lane in both roles)
// Padded one t-row so the recur prefetch never reads OOB.
__device__ __align__(16) float g_zx[(size_t)(NROWS + BATCH) * 32];

// Ready flags: one per gemm tile (128 rows = quarter of one t).
// fidx = t*4 + qt, qt = b>>7.  [0,1024) real, [1024,1152) pad preset to 1.
#define NFLAG_REAL 1024
#define NFLAG_PAD  1152
__device__ unsigned g_flag[NFLAG_PAD];

typedef unsigned long long ull;

__device__ __forceinline__ void ffma2(ull &d, ull a, ull b) {
    asm("fma.rn.f32x2 %0, %1, %2, %0;" : "+l"(d) : "l"(a), "l"(b));
}
__device__ __forceinline__ float tanh_approx(float x) {
    float y; asm("tanh.approx.f32 %0, %1;" : "=f"(y) : "f"(x)); return y;
}
__device__ __forceinline__ void cpasync16(void* dst, const void* src) {
    unsigned ds = (unsigned)__cvta_generic_to_shared(dst);
    asm volatile("cp.async.cg.shared.global [%0], [%1], 16;" :: "r"(ds), "l"(src));
}
__device__ __forceinline__ void cp_commit() { asm volatile("cp.async.commit_group;"); }
template <int N> __device__ __forceinline__ void cp_wait() {
    asm volatile("cp.async.wait_group %0;" :: "n"(N));
}
__device__ __forceinline__ unsigned ld_acq(const unsigned* p) {
    unsigned v; asm volatile("ld.acquire.gpu.global.b32 %0, [%1];" : "=r"(v) : "l"(p)); return v;
}
__device__ __forceinline__ unsigned ld_rlx(const unsigned* p) {
    unsigned v; asm volatile("ld.relaxed.gpu.global.b32 %0, [%1];" : "=r"(v) : "l"(p)); return v;
}
__device__ __forceinline__ void st_rel(unsigned* p, unsigned v) {
    asm volatile("st.release.gpu.global.b32 [%0], %1;" :: "l"(p), "r"(v));
}
__device__ __forceinline__ void fence_acq() {
    asm volatile("fence.acq_rel.gpu;" ::: "memory");
}

// Sync-free warp-convergent smem exchange primitives (r13-proven).
__device__ __forceinline__ void sts_x(unsigned a, float v) {
    asm volatile("st.volatile.shared.f32 [%0], %1;" :: "r"(a), "f"(v));
}
__device__ __forceinline__ float4 lds128_x(unsigned a) {
    float4 r;
    asm volatile("ld.volatile.shared.v4.f32 {%0,%1,%2,%3}, [%4];"
                 : "=f"(r.x), "=f"(r.y), "=f"(r.z), "=f"(r.w) : "r"(a));
    return r;
}

__global__ void init_flags() {
    int i = blockIdx.x * blockDim.x + threadIdx.x;
    if (i < NFLAG_PAD) g_flag[i] = (i < NFLAG_REAL) ? 0u : 1u;
}

// ---------------------------------------------------------------------------
// Fused kernel. Blocks 0..63: recur — hybrid exchanges: smem window for the
// prefix (ex1), INDEPENDENT PARALLEL SHFL.IDX for fiuo gather (ex2) and h
// broadcast (ex3). Blocks 64..1087: gemm, r15-identical 2-D lane tile.
// ---------------------------------------------------------------------------
#define GEMM_BLOCKS 1024
#define RECUR_BLOCKS 64
#define KCH    32
#define NCHUNK 8
#define WIN    16

union SmemU {
    struct { float w_s[32 * 256]; float xs[2][128 * 32]; } g;  // 32KB + 32KB
    float ex[8][40];    // per warp: cv[32], pad
};

__global__ void __launch_bounds__(256)
qlstm_fused(const float* __restrict__ x,
            const float* __restrict__ Wf, const float* __restrict__ bf,
            const float* __restrict__ Wi, const float* __restrict__ bi,
            const float* __restrict__ Wu, const float* __restrict__ bu,
            const float* __restrict__ Wo, const float* __restrict__ bo,
            const float* __restrict__ pf, const float* __restrict__ pi_,
            const float* __restrict__ pu, const float* __restrict__ po,
            float* __restrict__ out)
{
    __shared__ __align__(16) SmemU sm;

    const int tid  = threadIdx.x;
    const int lane = tid & 31;
    const unsigned FULL = 0xFFFFFFFFu;

    if (blockIdx.x >= RECUR_BLOCKS) {
        // ================= GEMM role: 128 rows = tile gb ===================
        const int gb   = blockIdx.x - RECUR_BLOCKS;
        const int warp = tid >> 5;
        const int ri   = lane >> 3;           // 0..3: row group within warp
        const int oi   = lane & 7;            // 0..7: output qubit
        const int row0  = gb * 128;
        const int wrow0 = warp * 16;

        float* w_s = sm.g.w_s;

        #pragma unroll
        for (int i = 0; i < 8; i++) {
            int idx = tid + 256 * i;
            int o = idx >> 6, s = idx & 63;
            int sw = (s & ~7) | ((s & 7) ^ (o & 7));
            int g = o >> 3, q = o & 7;
            const float* base = (g == 0 ? Wf : (g == 1 ? Wi : (g == 2 ? Wu : Wo)));
            cpasync16(&w_s[o * 256 + sw * 4], base + q * DIN + s * 4);
        }

        auto load_x = [&](int kc, int buf) {
            #pragma unroll
            for (int i = 0; i < 4; i++) {
                int idx = tid + 256 * i;          // 1024 slots: 128 rows x 8
                int r = idx >> 3, s = idx & 7;
                int sw2 = s ^ ((r >> 2) & 3);
                cpasync16(&sm.g.xs[buf][r * 32 + sw2 * 4],
                          x + (size_t)(row0 + r) * IN_DIM + kc * KCH + s * 4);
            }
        };

        load_x(0, 0); cp_commit();                // group: {W, x0}

        ull acc[4][4];
        #pragma unroll
        for (int rr = 0; rr < 4; rr++)
            #pragma unroll
            for (int m = 0; m < 4; m++) acc[rr][m] = 0ULL;

        #pragma unroll 1
        for (int kc = 0; kc < NCHUNK; kc++) {
            if (kc < NCHUNK - 1) { load_x(kc + 1, (kc + 1) & 1); cp_commit(); }
            if (kc < NCHUNK - 1) cp_wait<1>(); else cp_wait<0>();
            __syncthreads();

            const float* xb = sm.g.xs[kc & 1];

            #pragma unroll
            for (int j = 0; j < 8; j++) {
                const int s  = kc * 8 + j;
                const int sw = (s & ~7) | ((s & 7) ^ oi);
                ulonglong2 wv[4];
                #pragma unroll
                for (int m = 0; m < 4; m++)
                    wv[m] = *reinterpret_cast<const ulonglong2*>(
                        &w_s[(oi + 8 * m) * 256 + sw * 4]);

                ulonglong2 xv[4];
                #pragma unroll
                for (int rr = 0; rr < 4; rr++) {
                    int r = wrow0 + 4 * ri + rr;
                    int sw2 = j ^ ((r >> 2) & 3);
                    xv[rr] = *reinterpret_cast<const ulonglong2*>(
                        &xb[r * 32 + sw2 * 4]);
                }

                #pragma unroll
                for (int rr = 0; rr < 4; rr++)
                    #pragma unroll
                    for (int m = 0; m < 4; m++) {
                        ffma2(acc[rr][m], xv[rr].x, wv[m].x);
                        ffma2(acc[rr][m], xv[rr].y, wv[m].y);
                    }
            }
            __syncthreads();
        }

        float bias[4] = { bf[oi], bi[oi], bu[oi], bo[oi] };

        #pragma unroll
        for (int rr = 0; rr < 4; rr++) {
            int row = row0 + wrow0 + 4 * ri + rr;
            #pragma unroll
            for (int m = 0; m < 4; m++) {
                float2 p = *reinterpret_cast<float2*>(&acc[rr][m]);
                g_zx[(size_t)row * 32 + m * 8 + oi] = p.x + p.y + bias[m];
            }
        }

        __syncthreads();
        if (tid == 0) st_rel(&g_flag[gb], 1u);     // fidx == gb == t*4 + qt
    } else {
        // ================= RECUR role: 8 chains per block ==================
        const int wid = tid >> 5;
        const int b   = blockIdx.x * 8 + wid;
        const int qt  = blockIdx.x >> 4;           // == b>>7, uniform per block
        const int g = lane >> 3, q = lane & 7;

        // smem only for exchange 1 (prefix window)
        float* exw = &sm.ex[wid][0];
        const unsigned cvb = (unsigned)__cvta_generic_to_shared(exw);
        const unsigned st1 = cvb + lane * 4;
        const unsigned rd1a = cvb + g * 32, rd1b = rd1a + 16;

        const float* W = (g == 0 ? Wf : (g == 1 ? Wi : (g == 2 ? Wu : Wo))) + q * DIN + IN_DIM;
        const float* p = (g == 0 ? pf : (g == 1 ? pi_ : (g == 2 ? pu : po)));

        float Whr[8];
        #pragma unroll
        for (int j = 0; j < 8; j++) Whr[j] = W[j];

        float cthp = (g == 2) ? 1.f : 0.5f;
        #pragma unroll
        for (int j = 0; j < 8; j++) if (j <= q) cthp *= __cosf(p[j]);
        const float s2 = (g == 2) ? 1.f : 0.5f;
        const float s3 = (g == 2) ? 0.f : 0.5f;

        const bool p1 = (q >= 1), p2 = (q >= 2), p3 = (q >= 3),
                   p4 = (q >= 4), p5 = (q >= 5), p6 = (q >= 6), p7 = (q >= 7);

        const float* zp = g_zx + (size_t)b * 32 + lane;
        const size_t zstr = (size_t)BATCH * 32;

        float* hx_out = out + (size_t)SEQ * BATCH * HDIM;
        float* cx_out = hx_out + (size_t)BATCH * HDIM;

        float h[8];
        #pragma unroll
        for (int j = 0; j < 8; j++) h[j] = 0.f;
        float c = 0.f, hnew = 0.f;

        unsigned fv[WIN];
        auto load_flags = [&](int w16) {
            #pragma unroll
            for (int i = 0; i < WIN; i++)
                fv[i] = ld_rlx(&g_flag[(w16 + 1 + i) * 4 + qt]);
        };

        {
            unsigned r = ld_acq(&g_flag[qt]);
            while (r == 0) { __nanosleep(128); r = ld_acq(&g_flag[qt]); }
        }
        load_flags(0);
        float zcur = zp[0];

        #pragma unroll 1
        for (int w = 0; w < SEQ / WIN; w++) {
            const int tw = w * WIN;

            unsigned allv = fv[0];
            #pragma unroll
            for (int i = 1; i < WIN; i++) allv &= fv[i];
            if (allv == 0) {
                #pragma unroll
                for (int i = 0; i < WIN; i++) {
                    while (fv[i] == 0) {
                        __nanosleep(128);
                        fv[i] = ld_rlx(&g_flag[(tw + 1 + i) * 4 + qt]);
                    }
                }
            }
            fence_acq();
            if (w < SEQ / WIN - 1) load_flags(tw + WIN);

            float hs[WIN];

            #pragma unroll
            for (int s = 0; s < WIN; s++) {
                const int t = tw + s;
                float zn = zp[(size_t)(t + 1) * zstr];

                // recurrent dot, tree-shaped (h register-replicated)
                float s01 = fmaf(h[1], Whr[1], h[0] * Whr[0]);
                float s23 = fmaf(h[3], Whr[3], h[2] * Whr[2]);
                float s45 = fmaf(h[5], Whr[5], h[4] * Whr[4]);
                float s67 = fmaf(h[7], Whr[7], h[6] * Whr[6]);
                float z = zcur + ((s01 + s23) + (s45 + s67));

                // exchange 1 (smem, sync-free): share RAW cos in gate group
                float cz = __cosf(z);
                sts_x(st1, cz);
                float4 va = lds128_x(rd1a);
                float4 vb = lds128_x(rd1b);

                float u1 = p1 ? va.y : 1.f, u2 = p2 ? va.z : 1.f, u3 = p3 ? va.w : 1.f;
                float u4 = p4 ? vb.x : 1.f, u5 = p5 ? vb.y : 1.f, u6 = p6 ? vb.z : 1.f;
                float u7 = p7 ? vb.w : 1.f;
                float pr = (((va.x * u1) * (u2 * u3)) * ((u4 * u5) * (u6 * u7))) * cthp;

                float th = tanh_approx(pr);
                float a  = fmaf(s2, th, s3);

                // exchange 2: fiuo gather — 4 INDEPENDENT shfl.idx
                float af = __shfl_sync(FULL, a, q);
                float ai = __shfl_sync(FULL, a, 8 + q);
                float au = __shfl_sync(FULL, a, 16 + q);
                float ao = __shfl_sync(FULL, a, 24 + q);

                c    = fmaf(af, c, ai * au);
                hnew = ao * tanh_approx(c);

                // exchange 3: h broadcast — 8 INDEPENDENT shfl.idx
                #pragma unroll
                for (int j = 0; j < 8; j++)
                    h[j] = __shfl_sync(FULL, hnew, j);

                hs[s] = hnew;
                zcur  = zn;
            }

            // batched, off-critical-path stores (4x same-addr dup, same value)
            #pragma unroll
            for (int s = 0; s < WIN; s++)
                out[(size_t)(tw + s) * (BATCH * HDIM) + (size_t)b * HDIM + q] = hs[s];
        }

        hx_out[(size_t)b * HDIM + q] = hnew;
        cx_out[(size_t)b * HDIM + q] = c;
    }
}

extern "C" void kernel_launch(void* const* d_in, const int* in_sizes, int n_in,
                              void* d_out, int out_size) {
    const float* inputs = (const float*)d_in[0];
    const float* Wf = (const float*)d_in[1];  const float* bf = (const float*)d_in[2];
    const float* Wi = (const float*)d_in[3];  const float* bi = (const float*)d_in[4];
    const float* Wu = (const float*)d_in[5];  const float* bu = (const float*)d_in[6];
    const float* Wo = (const float*)d_in[7];  const float* bo = (const float*)d_in[8];
    const float* pf  = (const float*)d_in[9];
    const float* pi_ = (const float*)d_in[10];
    const float* pu  = (const float*)d_in[11];
    const float* po  = (const float*)d_in[12];
    float* out = (float*)d_out;

    init_flags<<<5, 256>>>();
    qlstm_fused<<<RECUR_BLOCKS + GEMM_BLOCKS, 256>>>(
        inputs, Wf, bf, Wi, bi, Wu, bu, Wo, bo, pf, pi_, pu, po, out);
}